// round 3
// baseline (speedup 1.0000x reference)
#include <cuda_runtime.h>

#define T_DIM 512
#define B_DIM 256
#define N_DIM 128
#define BN    (B_DIM * N_DIM)
#define NCHUNK 32
#define TCHUNK (T_DIM / NCHUNK)

#define LOGC_F 5.545177444479562f   /* ln 256 */
#define LOGC_D 5.545177444479562

// Scratch (device globals; no allocation allowed)
__device__ float g_score[B_DIM];
__device__ float g_logZ[B_DIM];
__device__ int   g_len[B_DIM];
__device__ float g_part_s[NCHUNK * B_DIM];
__device__ int   g_part_c[NCHUNK * B_DIM];
__device__ int2  g_sched[B_DIM / 2];

// ---------------- f32x2 helpers (packed dual fp32 FMA, sm_100+) -------------
__device__ __forceinline__ unsigned long long pack2(float lo, float hi) {
    unsigned long long u;
    asm("mov.b64 %0, {%1,%2};" : "=l"(u) : "f"(lo), "f"(hi));
    return u;
}
__device__ __forceinline__ void unpack2(unsigned long long u, float& lo, float& hi) {
    asm("mov.b64 {%0,%1}, %2;" : "=f"(lo), "=f"(hi) : "l"(u));
}
__device__ __forceinline__ void ffma2(unsigned long long& d,
                                      unsigned long long a, unsigned long long b) {
    asm("fma.rn.f32x2 %0, %1, %2, %0;" : "+l"(d) : "l"(a), "l"(b));
}

// ---------------------------------------------------------------------------
// A1: coalesced partial gold-path score + count over a t-chunk. thread = b.
// ---------------------------------------------------------------------------
__global__ void scoreA1(const float* __restrict__ emit,
                        const int*   __restrict__ target,
                        const int*   __restrict__ mask,
                        const float* __restrict__ trans) {
    const int b = threadIdx.x;
    const int c = blockIdx.x;
    const int t0 = c * TCHUNK;
    float s = 0.f; int cnt = 0;
    #pragma unroll
    for (int t = t0; t < t0 + TCHUNK; ++t) {
        if (mask[t * B_DIM + b] != 0) {
            int tg = target[t * B_DIM + b];
            float v = emit[(size_t)t * BN + b * N_DIM + tg];
            if (t > 0) {
                int tp = target[(t - 1) * B_DIM + b];
                v += trans[tp * N_DIM + tg];
            }
            s += v; cnt += 1;
        }
    }
    g_part_s[c * B_DIM + b] = s;
    g_part_c[c * B_DIM + b] = cnt;
}

// ---------------------------------------------------------------------------
// A2: combine partials, add start/end bonuses, then bitonic-sort b by length
// and emit the longest+shortest pairing schedule. One CTA, thread = b.
// ---------------------------------------------------------------------------
__global__ void scoreA2(const int*   __restrict__ target,
                        const float* __restrict__ strans,
                        const float* __restrict__ etrans) {
    __shared__ int key[B_DIM];
    const int b = threadIdx.x;
    float s = 0.f; int cnt = 0;
    for (int c = 0; c < NCHUNK; ++c) {
        s   += g_part_s[c * B_DIM + b];
        cnt += g_part_c[c * B_DIM + b];
    }
    s += strans[target[b]];
    s += etrans[target[(cnt - 1) * B_DIM + b]];
    g_score[b] = s;
    g_len[b]   = cnt;
    key[b] = (cnt << 9) | b;           // unique keys -> deterministic sort
    __syncthreads();

    // bitonic sort ascending on key
    for (int k = 2; k <= B_DIM; k <<= 1) {
        for (int j = k >> 1; j > 0; j >>= 1) {
            int p = b ^ j;
            if (p > b) {
                int a0 = key[b], a1 = key[p];
                bool asc = ((b & k) == 0);
                if ((a0 > a1) == asc) { key[b] = a1; key[p] = a0; }
            }
            __syncthreads();
        }
    }
    if (b < B_DIM / 2) {
        // pair longest (from back) with shortest (from front)
        g_sched[b] = make_int2(key[B_DIM - 1 - b] & 511, key[b] & 511);
    }
}

// ---------------------------------------------------------------------------
// Forward kernel: 128 CTAs, each runs 2 batch elements sequentially.
// 256 threads: h = tid&3 (K-quarter of 32 i's), jp = tid>>2 (output pair
// j0=2jp, j1=2jp+1). E pairs in registers as f32x2 operands.
// p stored duplicated (p_i,p_i) in smem with XOR line swizzle; double-buffered;
// ONE barrier per step. Constant normalizer exp(-ln256) per step; exact
// renormalization every 8 steps.
// ---------------------------------------------------------------------------
__global__ void __launch_bounds__(256, 1)
forward_kernel(const float* __restrict__ emit,
               const float* __restrict__ trans,
               const float* __restrict__ strans,
               const float* __restrict__ etrans) {
    __shared__ float4 pbuf[2][64];   // 64 lines x 16B, swizzled
    __shared__ float  wsum[8];

    const int tid  = threadIdx.x;
    const int lane = tid & 31;
    const int warp = tid >> 5;
    const int h    = tid & 3;            // K-quarter
    const int jp   = tid >> 2;           // 0..63
    const int j0   = 2 * jp, j1 = j0 + 1;
    const bool prod = (h == 0);
    const int  cxor = h << 1;            // 2h, swizzle key
    const int  qsto = jp ^ ((jp >> 4) << 1);   // store line for producer

    // E pairs: i = h*32 + k2 -> (E[i][j0], E[i][j1])
    unsigned long long E2[32];
    #pragma unroll
    for (int k2 = 0; k2 < 32; ++k2) {
        int i = h * 32 + k2;
        E2[k2] = pack2(__expf(trans[i * N_DIM + j0]),
                       __expf(trans[i * N_DIM + j1]));
    }
    const float et0 = __expf(etrans[j0]);
    const float et1 = __expf(etrans[j1]);

    const int2 sched = g_sched[blockIdx.x];

    #pragma unroll 1
    for (int pi = 0; pi < 2; ++pi) {
        const int b   = (pi == 0) ? sched.x : sched.y;
        const int len = g_len[b];
        const float* eb = emit + (size_t)b * N_DIM;

        double acc_log = 0.0;
        float v0 = 0.f, v1 = 0.f;
        float2 ecur = make_float2(0.f, 0.f);

        if (prod) {
            float a0 = strans[j0] + eb[j0];
            float a1 = strans[j1] + eb[j1];
            v0 = __expf(a0); v1 = __expf(a1);
            pbuf[0][qsto] = make_float4(v0, v0, v1, v1);
            if (len > 1)
                ecur = *(const float2*)(eb + (size_t)BN + j0);
        }
        __syncthreads();

        #pragma unroll 1
        for (int t = 1; t < len; ++t) {
            float2 enxt = make_float2(0.f, 0.f);
            if (prod && t + 1 < len)
                enxt = *(const float2*)(eb + (size_t)(t + 1) * BN + j0);

            const ulonglong2* rb =
                (const ulonglong2*)pbuf[(t - 1) & 1] ;

            unsigned long long acc0 = 0ull, acc1 = 0ull;
            #pragma unroll
            for (int k = 0; k < 16; ++k) {
                ulonglong2 pa = rb[(h << 4) + (k ^ cxor)];
                ffma2(acc0, pa.x, E2[2 * k]);
                ffma2(acc1, pa.y, E2[2 * k + 1]);
            }
            float x0, y0, x1, y1;
            unpack2(acc0, x0, y0);
            unpack2(acc1, x1, y1);
            float s0 = x0 + x1;          // partial for j0 over my 32 i's
            float s1 = y0 + y1;          // partial for j1
            // combine K-quarters (h = lane&3)
            s0 += __shfl_xor_sync(0xffffffffu, s0, 1);
            s1 += __shfl_xor_sync(0xffffffffu, s1, 1);
            s0 += __shfl_xor_sync(0xffffffffu, s0, 2);
            s1 += __shfl_xor_sync(0xffffffffu, s1, 2);

            float nv0 = 0.f, nv1 = 0.f;
            if (prod) {
                nv0 = s0 * __expf(ecur.x - LOGC_F);
                nv1 = s1 * __expf(ecur.y - LOGC_F);
            }

            if ((t & 7) == 0) {          // exact renormalization
                float r = prod ? (nv0 + nv1) : 0.f;
                #pragma unroll
                for (int o = 16; o; o >>= 1)
                    r += __shfl_xor_sync(0xffffffffu, r, o);
                if (lane == 0) wsum[warp] = r;
                __syncthreads();
                float ssum = wsum[0] + wsum[1] + wsum[2] + wsum[3]
                           + wsum[4] + wsum[5] + wsum[6] + wsum[7];
                float inv = 1.f / ssum;
                nv0 *= inv; nv1 *= inv;
                if (tid == 0) acc_log += log((double)ssum);
            }

            if (prod) {
                pbuf[t & 1][qsto] = make_float4(nv0, nv0, nv1, nv1);
                v0 = nv0; v1 = nv1;
            }
            ecur = enxt;
            __syncthreads();
        }

        // finalize: logZ_b = acc_log + (len-1)*ln256 + log( sum_j p_j e^{etrans_j} )
        float r = prod ? (v0 * et0 + v1 * et1) : 0.f;
        #pragma unroll
        for (int o = 16; o; o >>= 1)
            r += __shfl_xor_sync(0xffffffffu, r, o);
        if (lane == 0) wsum[warp] = r;
        __syncthreads();
        if (tid == 0) {
            float tot = wsum[0] + wsum[1] + wsum[2] + wsum[3]
                      + wsum[4] + wsum[5] + wsum[6] + wsum[7];
            g_logZ[b] = (float)(acc_log + (double)(len - 1) * LOGC_D
                                + log((double)tot));
        }
        __syncthreads();   // protect wsum/pbuf reuse for second b
    }
}

// ---------------------------------------------------------------------------
// Final deterministic fp64 reduction -> (logZ - score) / B
// ---------------------------------------------------------------------------
__global__ void reduce_kernel(float* __restrict__ out) {
    __shared__ double sh[B_DIM];
    int tid = threadIdx.x;
    sh[tid] = (double)g_logZ[tid] - (double)g_score[tid];
    __syncthreads();
    for (int o = B_DIM / 2; o; o >>= 1) {
        if (tid < o) sh[tid] += sh[tid + o];
        __syncthreads();
    }
    if (tid == 0) out[0] = (float)(sh[0] / (double)B_DIM);
}

extern "C" void kernel_launch(void* const* d_in, const int* in_sizes, int n_in,
                              void* d_out, int out_size) {
    const float* emit   = (const float*)d_in[0];
    const int*   target = (const int*)d_in[1];
    const int*   mask   = (const int*)d_in[2];
    const float* trans  = (const float*)d_in[3];
    const float* strans = (const float*)d_in[4];
    const float* etrans = (const float*)d_in[5];

    scoreA1<<<NCHUNK, B_DIM>>>(emit, target, mask, trans);
    scoreA2<<<1, B_DIM>>>(target, strans, etrans);
    forward_kernel<<<B_DIM / 2, 256>>>(emit, trans, strans, etrans);
    reduce_kernel<<<1, B_DIM>>>((float*)d_out);
}

// round 4
// speedup vs baseline: 2.1872x; 2.1872x over previous
#include <cuda_runtime.h>

#define T_DIM 512
#define B_DIM 256
#define N_DIM 128
#define BN    (B_DIM * N_DIM)
#define NCHUNK 32
#define TCHUNK (T_DIM / NCHUNK)
#define NSING 40
#define NPAIR ((B_DIM - NSING) / 2)   /* 108 */
#define NCTA  (NSING + NPAIR)         /* 148 */

#define LOGC_F 5.545177444479562f     /* ln 256 */
#define LOGC_D 5.545177444479562

__device__ float g_score[B_DIM];
__device__ float g_logZ[B_DIM];
__device__ int   g_len[B_DIM];
__device__ float g_part_s[NCHUNK * B_DIM];
__device__ int   g_part_c[NCHUNK * B_DIM];
__device__ int2  g_sched[NCTA];

// ---------------- f32x2 helpers (packed dual fp32 FMA, sm_100+) -------------
__device__ __forceinline__ unsigned long long pack2(float lo, float hi) {
    unsigned long long u;
    asm("mov.b64 %0, {%1,%2};" : "=l"(u) : "f"(lo), "f"(hi));
    return u;
}
__device__ __forceinline__ void unpack2(unsigned long long u, float& lo, float& hi) {
    asm("mov.b64 {%0,%1}, %2;" : "=f"(lo), "=f"(hi) : "l"(u));
}
__device__ __forceinline__ void ffma2(unsigned long long& d,
                                      unsigned long long a, unsigned long long b) {
    asm("fma.rn.f32x2 %0, %1, %2, %0;" : "+l"(d) : "l"(a), "l"(b));
}

// ---------------------------------------------------------------------------
// A1: coalesced partial gold-path score + count over a t-chunk. thread = b.
// ---------------------------------------------------------------------------
__global__ void scoreA1(const float* __restrict__ emit,
                        const int*   __restrict__ target,
                        const int*   __restrict__ mask,
                        const float* __restrict__ trans) {
    const int b = threadIdx.x;
    const int c = blockIdx.x;
    const int t0 = c * TCHUNK;
    float s = 0.f; int cnt = 0;
    #pragma unroll
    for (int t = t0; t < t0 + TCHUNK; ++t) {
        if (mask[t * B_DIM + b] != 0) {
            int tg = target[t * B_DIM + b];
            float v = emit[(size_t)t * BN + b * N_DIM + tg];
            if (t > 0) {
                int tp = target[(t - 1) * B_DIM + b];
                v += trans[tp * N_DIM + tg];
            }
            s += v; cnt += 1;
        }
    }
    g_part_s[c * B_DIM + b] = s;
    g_part_c[c * B_DIM + b] = cnt;
}

// ---------------------------------------------------------------------------
// A2: combine partials + bonuses; bitonic sort by length (asc); schedule:
// 108 pair-CTAs take the 216 shortest (adjacent pairing), 40 single-CTAs
// take the 40 longest.
// ---------------------------------------------------------------------------
__global__ void scoreA2(const int*   __restrict__ target,
                        const float* __restrict__ strans,
                        const float* __restrict__ etrans) {
    __shared__ int key[B_DIM];
    const int b = threadIdx.x;
    float s = 0.f; int cnt = 0;
    for (int c = 0; c < NCHUNK; ++c) {
        s   += g_part_s[c * B_DIM + b];
        cnt += g_part_c[c * B_DIM + b];
    }
    s += strans[target[b]];
    s += etrans[target[(cnt - 1) * B_DIM + b]];
    g_score[b] = s;
    g_len[b]   = cnt;
    key[b] = (cnt << 9) | b;
    __syncthreads();

    for (int k = 2; k <= B_DIM; k <<= 1) {
        for (int jj = k >> 1; jj > 0; jj >>= 1) {
            int p = b ^ jj;
            if (p > b) {
                int a0 = key[b], a1 = key[p];
                bool asc = ((b & k) == 0);
                if ((a0 > a1) == asc) { key[b] = a1; key[p] = a0; }
            }
            __syncthreads();
        }
    }
    if (b < NPAIR) {
        g_sched[b] = make_int2(key[2 * b] & 511, key[2 * b + 1] & 511);
    } else if (b < NCTA) {
        g_sched[b] = make_int2(key[2 * NPAIR + (b - NPAIR)] & 511, -1);
    }
}

// ---------------------------------------------------------------------------
// Forward kernel. 148 CTAs x 256 threads.
// pair mode : 2 concurrent chains (128 threads each), thread owns one j,
//             full-K dot via f32x2 with i-pair packing, named barrier/chain.
// single mode: 1 chain, 256 threads, K-split h=tid&1, shfl_xor(1) combine.
// p in smem plain (no duplication); broadcast float4 reads (1 wavefront).
// emit prefetched 4 steps ahead; renorm every 16 steps, float __logf.
// ---------------------------------------------------------------------------
__global__ void __launch_bounds__(256, 1)
forward_kernel(const float* __restrict__ emit,
               const float* __restrict__ trans,
               const float* __restrict__ strans,
               const float* __restrict__ etrans) {
    __shared__ __align__(16) float pbuf[2][2][N_DIM];
    __shared__ float wsum[16];

    const int tid  = threadIdx.x;
    const int lane = tid & 31;
    const int2 sc  = g_sched[blockIdx.x];

    if (sc.y >= 0) {
        // ================= PAIR MODE =================
        const int chain = tid >> 7;
        const int j     = tid & 127;
        const int b     = chain ? sc.y : sc.x;
        const int len   = g_len[b];
        const float* eb = emit + b * N_DIM + j;
        const int barid = 1 + chain;
        const int w4    = (tid >> 5) & 3;

        float eq[4];
        #pragma unroll
        for (int q = 0; q < 4; ++q) {
            int tq = 1 + q; if (tq > len - 1) tq = len - 1;
            eq[q] = eb[(size_t)tq * BN];
        }

        float v = __expf(strans[j] + eb[0]);
        pbuf[chain][0][j] = v;

        unsigned long long E2[64];
        #pragma unroll
        for (int m = 0; m < 64; ++m)
            E2[m] = pack2(__expf(trans[(2 * m) * N_DIM + j]),
                          __expf(trans[(2 * m + 1) * N_DIM + j]));
        const float etr = __expf(etrans[j]);

        float acc_log = 0.f;
        asm volatile("bar.sync %0, 128;" :: "r"(barid) : "memory");

        #pragma unroll 1
        for (int t = 1; t < len; ++t) {
            float ec = eq[(t - 1) & 3];
            int tn = t + 4; if (tn > len - 1) tn = len - 1;
            eq[(t - 1) & 3] = eb[(size_t)tn * BN];
            float ee = __expf(ec - LOGC_F);

            const ulonglong2* pu = (const ulonglong2*)pbuf[chain][(t - 1) & 1];
            unsigned long long a0 = 0ull, a1 = 0ull, a2 = 0ull, a3 = 0ull;
            #pragma unroll
            for (int k = 0; k < 32; k += 2) {
                ulonglong2 x = pu[k];
                ulonglong2 y = pu[k + 1];
                ffma2(a0, x.x, E2[2 * k]);
                ffma2(a1, x.y, E2[2 * k + 1]);
                ffma2(a2, y.x, E2[2 * k + 2]);
                ffma2(a3, y.y, E2[2 * k + 3]);
            }
            float f0, f1, f2, f3, f4, f5, f6, f7;
            unpack2(a0, f0, f1); unpack2(a1, f2, f3);
            unpack2(a2, f4, f5); unpack2(a3, f6, f7);
            float s = ((f0 + f1) + (f2 + f3)) + ((f4 + f5) + (f6 + f7));
            v = s * ee;

            if ((t & 15) == 0) {
                float r = v;
                #pragma unroll
                for (int o = 16; o; o >>= 1)
                    r += __shfl_xor_sync(0xffffffffu, r, o);
                if (lane == 0) wsum[chain * 4 + w4] = r;
                asm volatile("bar.sync %0, 128;" :: "r"(barid) : "memory");
                float ssum = wsum[chain * 4 + 0] + wsum[chain * 4 + 1]
                           + wsum[chain * 4 + 2] + wsum[chain * 4 + 3];
                v *= (1.f / ssum);
                acc_log += __logf(ssum);
            }

            pbuf[chain][t & 1][j] = v;
            asm volatile("bar.sync %0, 128;" :: "r"(barid) : "memory");
        }

        // finalize
        float r = v * etr;
        #pragma unroll
        for (int o = 16; o; o >>= 1)
            r += __shfl_xor_sync(0xffffffffu, r, o);
        if (lane == 0) wsum[chain * 4 + w4] = r;
        asm volatile("bar.sync %0, 128;" :: "r"(barid) : "memory");
        if (j == 0) {
            float tot = wsum[chain * 4 + 0] + wsum[chain * 4 + 1]
                      + wsum[chain * 4 + 2] + wsum[chain * 4 + 3];
            g_logZ[b] = (float)((double)acc_log + (double)(len - 1) * LOGC_D
                                + log((double)tot));
        }
    } else {
        // ================= SINGLE MODE =================
        const int b   = sc.x;
        const int len = g_len[b];
        const int j   = tid >> 1;
        const int h   = tid & 1;
        const int h4  = h ? 4 : 0;
        const float* eb = emit + b * N_DIM + j;
        const int warp  = tid >> 5;

        float eq[4];
        #pragma unroll
        for (int q = 0; q < 4; ++q) {
            int tq = 1 + q; if (tq > len - 1) tq = len - 1;
            eq[q] = eb[(size_t)tq * BN];
        }

        float v = __expf(strans[j] + eb[0]);
        if (h == 0) pbuf[0][0][j] = v;

        unsigned long long E2[32];
        #pragma unroll
        for (int k = 0; k < 16; ++k) {
            int bi = 64 * h + 4 * (k ^ h4);
            E2[2 * k]     = pack2(__expf(trans[(bi    ) * N_DIM + j]),
                                  __expf(trans[(bi + 1) * N_DIM + j]));
            E2[2 * k + 1] = pack2(__expf(trans[(bi + 2) * N_DIM + j]),
                                  __expf(trans[(bi + 3) * N_DIM + j]));
        }
        const float etr = __expf(etrans[j]);

        float acc_log = 0.f;
        __syncthreads();

        #pragma unroll 1
        for (int t = 1; t < len; ++t) {
            float ec = eq[(t - 1) & 3];
            int tn = t + 4; if (tn > len - 1) tn = len - 1;
            eq[(t - 1) & 3] = eb[(size_t)tn * BN];
            float ee = __expf(ec - LOGC_F);

            const ulonglong2* pu = (const ulonglong2*)pbuf[0][(t - 1) & 1];
            unsigned long long a0 = 0ull, a1 = 0ull, a2 = 0ull, a3 = 0ull;
            #pragma unroll
            for (int k = 0; k < 16; k += 2) {
                ulonglong2 x = pu[16 * h + (k ^ h4)];
                ulonglong2 y = pu[16 * h + ((k + 1) ^ h4)];
                ffma2(a0, x.x, E2[2 * k]);
                ffma2(a1, x.y, E2[2 * k + 1]);
                ffma2(a2, y.x, E2[2 * k + 2]);
                ffma2(a3, y.y, E2[2 * k + 3]);
            }
            float f0, f1, f2, f3, f4, f5, f6, f7;
            unpack2(a0, f0, f1); unpack2(a1, f2, f3);
            unpack2(a2, f4, f5); unpack2(a3, f6, f7);
            float s = ((f0 + f1) + (f2 + f3)) + ((f4 + f5) + (f6 + f7));
            s += __shfl_xor_sync(0xffffffffu, s, 1);   // combine K-halves
            v = s * ee;

            if ((t & 15) == 0) {
                float r = v;
                #pragma unroll
                for (int o = 16; o; o >>= 1)
                    r += __shfl_xor_sync(0xffffffffu, r, o);
                if (lane == 0) wsum[warp] = r;
                __syncthreads();
                float ssum = 0.5f * (((wsum[0] + wsum[1]) + (wsum[2] + wsum[3]))
                                   + ((wsum[4] + wsum[5]) + (wsum[6] + wsum[7])));
                v *= (1.f / ssum);
                acc_log += __logf(ssum);
            }

            if (h == 0) pbuf[0][t & 1][j] = v;
            __syncthreads();
        }

        // finalize
        float r = v * etr;
        #pragma unroll
        for (int o = 16; o; o >>= 1)
            r += __shfl_xor_sync(0xffffffffu, r, o);
        if (lane == 0) wsum[warp] = r;
        __syncthreads();
        if (tid == 0) {
            float tot = 0.5f * (((wsum[0] + wsum[1]) + (wsum[2] + wsum[3]))
                              + ((wsum[4] + wsum[5]) + (wsum[6] + wsum[7])));
            g_logZ[b] = (float)((double)acc_log + (double)(len - 1) * LOGC_D
                                + log((double)tot));
        }
    }
}

// ---------------------------------------------------------------------------
// Final deterministic fp64 reduction -> (logZ - score) / B
// ---------------------------------------------------------------------------
__global__ void reduce_kernel(float* __restrict__ out) {
    __shared__ double sh[B_DIM];
    int tid = threadIdx.x;
    sh[tid] = (double)g_logZ[tid] - (double)g_score[tid];
    __syncthreads();
    for (int o = B_DIM / 2; o; o >>= 1) {
        if (tid < o) sh[tid] += sh[tid + o];
        __syncthreads();
    }
    if (tid == 0) out[0] = (float)(sh[0] / (double)B_DIM);
}

extern "C" void kernel_launch(void* const* d_in, const int* in_sizes, int n_in,
                              void* d_out, int out_size) {
    const float* emit   = (const float*)d_in[0];
    const int*   target = (const int*)d_in[1];
    const int*   mask   = (const int*)d_in[2];
    const float* trans  = (const float*)d_in[3];
    const float* strans = (const float*)d_in[4];
    const float* etrans = (const float*)d_in[5];

    scoreA1<<<NCHUNK, B_DIM>>>(emit, target, mask, trans);
    scoreA2<<<1, B_DIM>>>(target, strans, etrans);
    forward_kernel<<<NCTA, 256>>>(emit, trans, strans, etrans);
    reduce_kernel<<<1, B_DIM>>>((float*)d_out);
}

// round 5
// speedup vs baseline: 3.1841x; 1.4558x over previous
#include <cuda_runtime.h>

#define T_DIM 512
#define B_DIM 256
#define N_DIM 128
#define BN    (B_DIM * N_DIM)
#define NCHUNK 64
#define TCHUNK (T_DIM / NCHUNK)
#define NCTA  (B_DIM / 2)            /* 128 forward CTAs */

#define LOGC_F 5.545177444479562f    /* ln 256 */
#define LOGC_D 5.545177444479562

__device__ float g_score[B_DIM];
__device__ float g_logZ[B_DIM];
__device__ int   g_len[B_DIM];
__device__ float g_part_s[NCHUNK * B_DIM];
__device__ int   g_part_c[NCHUNK * B_DIM];
__device__ int2  g_sched[NCTA];
__device__ unsigned int g_done;      /* zero-init; self-resetting */

// ---------------- f32x2 helpers (packed dual fp32 FMA, sm_100+) -------------
__device__ __forceinline__ unsigned long long pack2(float lo, float hi) {
    unsigned long long u;
    asm("mov.b64 %0, {%1,%2};" : "=l"(u) : "f"(lo), "f"(hi));
    return u;
}
__device__ __forceinline__ void unpack2(unsigned long long u, float& lo, float& hi) {
    asm("mov.b64 {%0,%1}, %2;" : "=f"(lo), "=f"(hi) : "l"(u));
}
__device__ __forceinline__ void ffma2(unsigned long long& d,
                                      unsigned long long a, unsigned long long b) {
    asm("fma.rn.f32x2 %0, %1, %2, %0;" : "+l"(d) : "l"(a), "l"(b));
}

// ---------------------------------------------------------------------------
// A1: coalesced partial gold-path score + count per t-chunk. thread = b.
// ---------------------------------------------------------------------------
__global__ void scoreA1(const float* __restrict__ emit,
                        const int*   __restrict__ target,
                        const int*   __restrict__ mask,
                        const float* __restrict__ trans) {
    const int b = threadIdx.x;
    const int c = blockIdx.x;
    const int t0 = c * TCHUNK;
    float s = 0.f; int cnt = 0;
    #pragma unroll
    for (int t = t0; t < t0 + TCHUNK; ++t) {
        if (mask[t * B_DIM + b] != 0) {
            int tg = target[t * B_DIM + b];
            float v = emit[(size_t)t * BN + b * N_DIM + tg];
            if (t > 0) {
                int tp = target[(t - 1) * B_DIM + b];
                v += trans[tp * N_DIM + tg];
            }
            s += v; cnt += 1;
        }
    }
    g_part_s[c * B_DIM + b] = s;
    g_part_c[c * B_DIM + b] = cnt;
}

// ---------------------------------------------------------------------------
// A2: combine partials + bonuses; bitonic sort by length; pairing schedule:
// CTA i gets (longest remaining, shortest remaining) -> pair sums ~equal,
// skewed pairs run mostly solo (cheap), overlapped pairs are short.
// ---------------------------------------------------------------------------
__global__ void scoreA2(const int*   __restrict__ target,
                        const float* __restrict__ strans,
                        const float* __restrict__ etrans) {
    __shared__ int key[B_DIM];
    const int b = threadIdx.x;
    float s = 0.f; int cnt = 0;
    for (int c = 0; c < NCHUNK; ++c) {
        s   += g_part_s[c * B_DIM + b];
        cnt += g_part_c[c * B_DIM + b];
    }
    s += strans[target[b]];
    s += etrans[target[(cnt - 1) * B_DIM + b]];
    g_score[b] = s;
    g_len[b]   = cnt;
    key[b] = (cnt << 9) | b;
    __syncthreads();

    for (int k = 2; k <= B_DIM; k <<= 1) {
        for (int jj = k >> 1; jj > 0; jj >>= 1) {
            int p = b ^ jj;
            if (p > b) {
                int a0 = key[b], a1 = key[p];
                bool asc = ((b & k) == 0);
                if ((a0 > a1) == asc) { key[b] = a1; key[p] = a0; }
            }
            __syncthreads();
        }
    }
    if (b < NCTA)
        g_sched[b] = make_int2(key[B_DIM - 1 - b] & 511, key[b] & 511);
}

// ---------------------------------------------------------------------------
// Forward kernel. 128 CTAs x 256 threads; 2 concurrent chains per CTA
// (chain = tid>>7), each chain 128 threads, thread owns one j, full-K f32x2
// dot from registers (E column in 128 regs). Named barrier per chain.
// Time loop unrolled x4: static ping-pong buffers + static 4-deep emit
// prefetch ring (no local memory). Renorm every 16 steps (float).
// Final (logZ - score)/B reduction fused via last-CTA pattern.
// ---------------------------------------------------------------------------
__global__ void __launch_bounds__(256, 1)
forward_kernel(const float* __restrict__ emit,
               const float* __restrict__ trans,
               const float* __restrict__ strans,
               const float* __restrict__ etrans,
               float* __restrict__ out) {
    __shared__ __align__(16) float pbuf[2][2][N_DIM];
    __shared__ float  wsum[8];
    __shared__ int    sflag;
    __shared__ double shd[256];

    const int tid   = threadIdx.x;
    const int lane  = tid & 31;
    const int chain = tid >> 7;
    const int j     = tid & 127;
    const int barid = 1 + chain;
    const int wslot = chain * 4 + ((tid >> 5) & 3);
    const int wbase = chain * 4;
    const int2 sc   = g_sched[blockIdx.x];

    const int b   = chain ? sc.y : sc.x;
    const int len = g_len[b];
    const float* eb = emit + b * N_DIM + j;

    // E column j as f32x2 pairs: E2[m] = (exp(trans[2m][j]), exp(trans[2m+1][j]))
    unsigned long long E2[64];
    #pragma unroll
    for (int m = 0; m < 64; ++m)
        E2[m] = pack2(__expf(trans[(2 * m) * N_DIM + j]),
                      __expf(trans[(2 * m + 1) * N_DIM + j]));
    const float etr = __expf(etrans[j]);

    float* pb0 = pbuf[chain][0];
    float* pb1 = pbuf[chain][1];

    float v = __expf(strans[j] + eb[0]);
    pb0[j] = v;
    float acc_log = 0.f;

    const int lm1 = len - 1;
    #define LDE(TT) eb[(size_t)(((TT) < lm1) ? (TT) : lm1) * BN]

    float e0 = LDE(1), e1 = LDE(2), e2 = LDE(3), e3 = LDE(4);

    asm volatile("bar.sync %0, 128;" :: "r"(barid) : "memory");

    #define STEP(EC, PR, PW, TT) do {                                        \
        float ee = __expf((EC) - LOGC_F);                                    \
        const ulonglong2* pu = (const ulonglong2*)(PR);                      \
        unsigned long long a0 = 0ull, a1 = 0ull, a2 = 0ull, a3 = 0ull;       \
        _Pragma("unroll")                                                    \
        for (int k = 0; k < 32; k += 2) {                                    \
            ulonglong2 x = pu[k];                                            \
            ulonglong2 y = pu[k + 1];                                        \
            ffma2(a0, x.x, E2[2 * k]);                                       \
            ffma2(a1, x.y, E2[2 * k + 1]);                                   \
            ffma2(a2, y.x, E2[2 * k + 2]);                                   \
            ffma2(a3, y.y, E2[2 * k + 3]);                                   \
        }                                                                    \
        float f0, f1, f2, f3, f4, f5, f6, f7;                                \
        unpack2(a0, f0, f1); unpack2(a1, f2, f3);                            \
        unpack2(a2, f4, f5); unpack2(a3, f6, f7);                            \
        v = (((f0 + f1) + (f2 + f3)) + ((f4 + f5) + (f6 + f7))) * ee;        \
        if (((TT) & 15) == 0) {                                              \
            float r = v;                                                     \
            _Pragma("unroll")                                                \
            for (int o = 16; o; o >>= 1)                                     \
                r += __shfl_xor_sync(0xffffffffu, r, o);                     \
            if (lane == 0) wsum[wslot] = r;                                  \
            asm volatile("bar.sync %0, 128;" :: "r"(barid) : "memory");      \
            float ss = wsum[wbase] + wsum[wbase + 1]                         \
                     + wsum[wbase + 2] + wsum[wbase + 3];                    \
            v *= (1.f / ss);                                                 \
            acc_log += __logf(ss);                                           \
        }                                                                    \
        (PW)[j] = v;                                                         \
        asm volatile("bar.sync %0, 128;" :: "r"(barid) : "memory");          \
    } while (0)

    int t = 1;
    #pragma unroll 1
    for (; t + 3 < len; t += 4) {
        float n0 = LDE(t + 4), n1 = LDE(t + 5), n2 = LDE(t + 6), n3 = LDE(t + 7);
        STEP(e0, pb0, pb1, t);
        STEP(e1, pb1, pb0, t + 1);
        STEP(e2, pb0, pb1, t + 2);
        STEP(e3, pb1, pb0, t + 3);
        e0 = n0; e1 = n1; e2 = n2; e3 = n3;
    }
    if (t < len) { STEP(e0, pb0, pb1, t); ++t; }
    if (t < len) { STEP(e1, pb1, pb0, t); ++t; }
    if (t < len) { STEP(e2, pb0, pb1, t); }

    // finalize: logZ_b
    float r = v * etr;
    #pragma unroll
    for (int o = 16; o; o >>= 1)
        r += __shfl_xor_sync(0xffffffffu, r, o);
    if (lane == 0) wsum[wslot] = r;
    asm volatile("bar.sync %0, 128;" :: "r"(barid) : "memory");
    if (j == 0) {
        float tot = wsum[wbase] + wsum[wbase + 1]
                  + wsum[wbase + 2] + wsum[wbase + 3];
        g_logZ[b] = (float)((double)acc_log + (double)(len - 1) * LOGC_D
                            + log((double)tot));
    }

    // ---- fused final reduction (last CTA) ----
    __syncthreads();
    if (tid == 0) {
        __threadfence();
        unsigned int old = atomicAdd(&g_done, 1u);
        sflag = (old == NCTA - 1) ? 1 : 0;
    }
    __syncthreads();
    if (sflag) {
        __threadfence();
        shd[tid] = (double)g_logZ[tid] - (double)g_score[tid];
        __syncthreads();
        for (int o = 128; o; o >>= 1) {
            if (tid < o) shd[tid] += shd[tid + o];
            __syncthreads();
        }
        if (tid == 0) {
            out[0] = (float)(shd[0] / (double)B_DIM);
            g_done = 0;   // self-reset for graph replay
        }
    }
    #undef STEP
    #undef LDE
}

extern "C" void kernel_launch(void* const* d_in, const int* in_sizes, int n_in,
                              void* d_out, int out_size) {
    const float* emit   = (const float*)d_in[0];
    const int*   target = (const int*)d_in[1];
    const int*   mask   = (const int*)d_in[2];
    const float* trans  = (const float*)d_in[3];
    const float* strans = (const float*)d_in[4];
    const float* etrans = (const float*)d_in[5];

    scoreA1<<<NCHUNK, B_DIM>>>(emit, target, mask, trans);
    scoreA2<<<1, B_DIM>>>(target, strans, etrans);
    forward_kernel<<<NCTA, 256>>>(emit, trans, strans, etrans, (float*)d_out);
}